// round 15
// baseline (speedup 1.0000x reference)
#include <cuda_runtime.h>
#include <math.h>
#include <stdint.h>

#define IN 8
#define HID 10
#define FEAT 200
#define H1 50
#define H2 10
#define ROWS_LOC 400    // gate rows per CTA (10 cells * 40)
#define PITCH 10        // W_ih padded 8->10; W_hh natural 10 (straight copy)

// Per-CTA dynamic shared layout (float offsets; keep vector targets 16B aligned)
#define OFF_WIH   0                             // 4000
#define OFF_WHH   (OFF_WIH + ROWS_LOC * PITCH)  // 4000 (16B aligned)
#define OFF_X     (OFF_WHH + ROWS_LOC * PITCH)  // 8000
#define OFF_H0    (OFF_X + IN)                  // 8008 (even)
#define OFF_FEAT  (OFF_H0 + 100)                // 8108 (mult of 4 -> 16B)
#define OFF_H1    (OFF_FEAT + FEAT)             // 8308
#define OFF_W2    (OFF_H1 + H1 + 2)             // 8360 (mult of 4 -> 16B)
#define SMEM_FLOATS (OFF_W2 + H2 * H1)          // 8860
#define SMEM_BYTES  (SMEM_FLOATS * 4)           // 35440

__device__ __forceinline__ float tanh_fast(float x) {
    float xc = fminf(fmaxf(x, -15.0f), 15.0f);
    float e = __expf(2.0f * xc);
    return __fdividef(e - 1.0f, e + 1.0f);
}
__device__ __forceinline__ float sigmoid_fast(float x) {
    float xc = fminf(fmaxf(x, -30.0f), 30.0f);
    return __fdividef(1.0f, 1.0f + __expf(-xc));
}
__device__ __forceinline__ uint32_t smem_u32(const void* p) {
    return (uint32_t)__cvta_generic_to_shared(p);
}
__device__ __forceinline__ void st_peer(uint32_t laddr, uint32_t peer, float v) {
    uint32_t rem;
    asm volatile("mapa.shared::cluster.u32 %0, %1, %2;"
                 : "=r"(rem) : "r"(laddr), "r"(peer));
    asm volatile("st.shared::cluster.u32 [%0], %1;"
                 :: "r"(rem), "r"(__float_as_uint(v)) : "memory");
}
__device__ __forceinline__ void cluster_sync_() {
    asm volatile("barrier.cluster.arrive.aligned;" ::: "memory");
    asm volatile("barrier.cluster.wait.aligned;" ::: "memory");
}
// ---- packed f32x2 helpers (sm_103a FFMA2 via PTX only) ----
__device__ __forceinline__ uint64_t pk2(float lo, float hi) {
    uint64_t r;
    asm("mov.b64 %0, {%1, %2};" : "=l"(r) : "f"(lo), "f"(hi));
    return r;
}
__device__ __forceinline__ uint64_t pkf2(float2 v) { return pk2(v.x, v.y); }
__device__ __forceinline__ float2 upk2(uint64_t v) {
    float2 r;
    asm("mov.b64 {%0, %1}, %2;" : "=f"(r.x), "=f"(r.y) : "l"(v));
    return r;
}
__device__ __forceinline__ uint64_t ffma2(uint64_t a, uint64_t b, uint64_t c) {
    uint64_t d;
    asm("fma.rn.f32x2 %0, %1, %2, %3;" : "=l"(d) : "l"(a), "l"(b), "l"(c));
    return d;
}

template <bool VEC>
__global__ __launch_bounds__(800, 1) __cluster_dims__(2, 1, 1)
void lstm_mlp_cluster(const float* __restrict__ x,
                      const float* __restrict__ h0,
                      const float* __restrict__ c0,
                      const float* __restrict__ W_ih,
                      const float* __restrict__ W_hh,
                      const float* __restrict__ b_ih,
                      const float* __restrict__ b_hh,
                      const float* __restrict__ W1,
                      const float* __restrict__ b1,
                      const float* __restrict__ W2,
                      const float* __restrict__ b2,
                      const float* __restrict__ W3,
                      const float* __restrict__ b3,
                      float* __restrict__ out)
{
    extern __shared__ float sm[];
    const int t = threadIdx.x;
    const int lane = t & 31;
    uint32_t rank;
    asm("mov.u32 %0, %%cluster_ctarank;" : "=r"(rank));
    const uint32_t peer = rank ^ 1u;

    // ---- Stage-1 mapping (warps 0..12): lane = 4q+g -> gate g of o = 8w+q
    const int o = (t >> 5) * 8 + (lane >> 2);
    const int g = lane & 3;
    const int oc = (o < 100) ? o : 99;           // clamp for safe reads
    const int cl = oc / 10;
    const int jj = oc - cl * 10;
    const int lr = cl * 40 + g * 10 + jj;        // local gate row 0..399

    // ---- Stage-3 mapping: 16 lanes per h1 row, 25 rows per CTA
    const int lane16 = t & 15;
    const int row_raw = t >> 4;
    const int row_loc = (row_raw < 25) ? row_raw : 24;
    const int row_glb = 25 * (int)rank + row_loc;

    // ================= Entry staging =================
    if (VEC) {
        // W_hh half: straight float4 copy (4000 floats = 1000 float4)
        const float4* wh4 = (const float4*)(W_hh + rank * (ROWS_LOC * HID));
        ((float4*)(sm + OFF_WHH))[t] = wh4[t];
        if (t < 200) ((float4*)(sm + OFF_WHH))[800 + t] = wh4[800 + t];
        // W_ih half: 800 float4, scatter 8->10 pitch via two STS.64
        const float4* wi4 = (const float4*)(W_ih + rank * (ROWS_LOC * IN));
        {
            float4 v = wi4[t];
            int e = t * 4;                                   // e&7 in {0,4}
            float2* dst = (float2*)(sm + OFF_WIH + (e >> 3) * PITCH + (e & 7));
            dst[0] = make_float2(v.x, v.y);
            dst[1] = make_float2(v.z, v.w);
        }
        if (rank == 0 && t < 125)
            ((float4*)(sm + OFF_W2))[t] = ((const float4*)W2)[t];
        if (t < 25)
            ((float4*)(sm + OFF_H0))[t] =
                ((const float4*)(h0 + (int)rank * 100))[t];
    } else {
        const float* wihg = W_ih + rank * (ROWS_LOC * IN);
        #pragma unroll
        for (int k = 0; k < 4; ++k) {
            int q = t + 800 * k;
            sm[OFF_WIH + (q >> 3) * PITCH + (q & 7)] = wihg[q];
        }
        const float* whhg = W_hh + rank * (ROWS_LOC * HID);
        #pragma unroll
        for (int k = 0; k < 5; ++k) {
            int q = t + 800 * k;
            sm[OFF_WHH + q] = whhg[q];
        }
        if (rank == 0 && t < H2 * H1) sm[OFF_W2 + t] = W2[t];
        if (t < 100) sm[OFF_H0 + t] = h0[(int)rank * 100 + t];
    }

    // Stage-1 per-thread operands
    float bias = 0.0f, c0r = 0.0f;
    if (t < 416) {
        int gr = (int)rank * ROWS_LOC + lr;
        bias = b_ih[gr] + b_hh[gr];
        if (o < 100) c0r = c0[(int)rank * 100 + o];
    }

    // Stage-3 W1 row slice in registers (16 lanes per row)
    float4 w1q[3];
    float  w1s[12];
    float4 w1tail = make_float4(0.f, 0.f, 0.f, 0.f);
    float  w1t = 0.0f, b1r = 0.0f;
    if (t < 416) {
        if (VEC) {
            const float4* w4p = (const float4*)(W1 + row_glb * FEAT); // 800B mult
            #pragma unroll
            for (int u = 0; u < 3; ++u) w1q[u] = w4p[lane16 + (u << 4)];
            if (lane16 < 2) w1tail = w4p[48 + lane16];
        } else {
            const float* w1p = W1 + row_glb * FEAT + lane16;
            #pragma unroll
            for (int u = 0; u < 12; ++u) w1s[u] = w1p[u << 4];
            w1t = (lane16 < 8) ? w1p[192] : 0.0f;
        }
        b1r = (lane16 == 0) ? b1[row_glb] : 0.0f;
    }

    // Stage-4/5 operands (CTA 0 only)
    float b2r = 0.0f, w3r = 0.0f, b3r = 0.0f;
    if (rank == 0) {
        if (t < H2) { b2r = b2[t]; w3r = W3[t]; }
        if (t == 0) b3r = b3[0];
    }
    if (t < IN) sm[OFF_X + t] = x[t];
    __syncthreads();   // CTA-local staging visible

    // ======== Stage 1+2: packed-f32x2 gate dots + activations + update ========
    if (t < 416) {
        const float2* wi2 = (const float2*)(sm + OFF_WIH + lr * PITCH);
        const float2* wh2 = (const float2*)(sm + OFF_WHH + lr * PITCH);
        const float2* x2  = (const float2*)(sm + OFF_X);
        const float2* h2v = (const float2*)(sm + OFF_H0 + cl * HID);
        uint64_t acc2 = pk2(bias, 0.0f);
        #pragma unroll
        for (int i = 0; i < 4; ++i)
            acc2 = ffma2(pkf2(wi2[i]), pkf2(x2[i]), acc2);
        #pragma unroll
        for (int k = 0; k < 5; ++k)
            acc2 = ffma2(pkf2(wh2[k]), pkf2(h2v[k]), acc2);
        float2 ar = upk2(acc2);
        float acc = ar.x + ar.y;

        float vin = (g == 2) ? (acc + acc) : acc;          // tanh = 2*sig(2x)-1
        float s   = sigmoid_fast(vin);
        float act = (g == 2) ? fmaf(2.0f, s, -1.0f) : s;

        const int base = lane & ~3;
        float ia = __shfl_sync(0xffffffffu, act, base);
        float fa = __shfl_sync(0xffffffffu, act, base + 1);
        float ga = __shfl_sync(0xffffffffu, act, base + 2);
        float oa = __shfl_sync(0xffffffffu, act, base + 3);
        if (g == 0 && o < 100) {
            float c = fmaf(fa, c0r, ia * ga);
            float h = oa * tanh_fast(c);
            int fidx = (rank == 1) ? o : (100 + o);        // gen bank first
            float* dst = sm + OFF_FEAT + fidx;
            *dst = h;
            st_peer(smem_u32(dst), peer, h);
        }
    }
    cluster_sync_();   // full feat visible in both CTAs

    // ======== Stage 3: 25 h1 rows per CTA, 16 lanes/row ========
    if (t < 416) {
        float sum = 0.0f;
        if (VEC) {
            const float4* f4 = (const float4*)(sm + OFF_FEAT);
            #pragma unroll
            for (int u = 0; u < 3; ++u) {
                float4 f = f4[lane16 + (u << 4)];
                float4 w = w1q[u];
                sum = fmaf(w.x, f.x, sum);
                sum = fmaf(w.y, f.y, sum);
                sum = fmaf(w.z, f.z, sum);
                sum = fmaf(w.w, f.w, sum);
            }
            if (lane16 < 2) {
                float4 f = f4[48 + lane16];
                sum = fmaf(w1tail.x, f.x, sum);
                sum = fmaf(w1tail.y, f.y, sum);
                sum = fmaf(w1tail.z, f.z, sum);
                sum = fmaf(w1tail.w, f.w, sum);
            }
        } else {
            const float* f = sm + OFF_FEAT;
            #pragma unroll
            for (int u = 0; u < 12; ++u)
                sum = fmaf(w1s[u], f[lane16 + (u << 4)], sum);
            if (lane16 < 8)
                sum = fmaf(w1t, f[192 + lane16], sum);
        }
        sum += __shfl_xor_sync(0xffffffffu, sum, 8);
        sum += __shfl_xor_sync(0xffffffffu, sum, 4);
        sum += __shfl_xor_sync(0xffffffffu, sum, 2);
        sum += __shfl_xor_sync(0xffffffffu, sum, 1);
        if (lane16 == 0 && row_raw < 25) {
            float v = tanh_fast(sum + b1r);
            if (rank == 0) sm[OFF_H1 + row_glb] = v;
            else           st_peer(smem_u32(sm + OFF_H1 + row_glb), 0u, v);
        }
    }
    cluster_sync_();   // CTA0 has all 50 h1 values

    // ======== Stage 4+5 (CTA0, warp 0) ========
    if (rank == 0 && t < 32) {
        float sum = 0.0f;
        if (t < H2) {
            const float* wv = sm + OFF_W2 + t * H1;
            const float* hv = sm + OFF_H1;
            #pragma unroll
            for (int i = 0; i < H1; ++i) sum = fmaf(wv[i], hv[i], sum);
        }
        float p = (t < H2) ? w3r * tanh_fast(sum + b2r) : 0.0f;
        #pragma unroll
        for (int m = 16; m > 0; m >>= 1)
            p += __shfl_xor_sync(0xffffffffu, p, m);
        if (t == 0) out[0] = tanh_fast(p + b3r);
    }
}

static inline bool aligned16(const void* p) {
    return (((uintptr_t)p) & 15u) == 0;
}

extern "C" void kernel_launch(void* const* d_in, const int* in_sizes, int n_in,
                              void* d_out, int out_size) {
    (void)in_sizes; (void)n_in; (void)out_size;
    const float* x    = (const float*)d_in[0];
    const float* h0   = (const float*)d_in[1];
    const float* c0   = (const float*)d_in[2];
    const float* W_ih = (const float*)d_in[3];
    const float* W_hh = (const float*)d_in[4];
    const float* b_ih = (const float*)d_in[5];
    const float* b_hh = (const float*)d_in[6];
    const float* W1   = (const float*)d_in[7];
    const float* b1   = (const float*)d_in[8];
    const float* W2   = (const float*)d_in[9];
    const float* b2   = (const float*)d_in[10];
    const float* W3   = (const float*)d_in[11];
    const float* b3   = (const float*)d_in[12];
    float* out = (float*)d_out;

    static bool attr_set = false;
    if (!attr_set) {
        cudaFuncSetAttribute(lstm_mlp_cluster<true>,
                             cudaFuncAttributeMaxDynamicSharedMemorySize,
                             SMEM_BYTES);
        cudaFuncSetAttribute(lstm_mlp_cluster<false>,
                             cudaFuncAttributeMaxDynamicSharedMemorySize,
                             SMEM_BYTES);
        attr_set = true;
    }

    const bool vec = aligned16(W_ih) && aligned16(W_hh) && aligned16(W1) &&
                     aligned16(h0) && aligned16(W2);

    if (vec) {
        lstm_mlp_cluster<true><<<2, 800, SMEM_BYTES>>>(
            x, h0, c0, W_ih, W_hh, b_ih, b_hh, W1, b1, W2, b2, W3, b3, out);
    } else {
        lstm_mlp_cluster<false><<<2, 800, SMEM_BYTES>>>(
            x, h0, c0, W_ih, W_hh, b_ih, b_hh, W1, b1, W2, b2, W3, b3, out);
    }
}

// round 16
// speedup vs baseline: 1.0568x; 1.0568x over previous
#include <cuda_runtime.h>
#include <math.h>
#include <stdint.h>

#define IN 8
#define HID 10
#define FEAT 200
#define H1 50
#define H2 10
#define ROWS_LOC 400    // gate rows per CTA (10 cells * 40)
#define PITCH 10        // W_ih padded 8->10; W_hh natural 10 (straight copy)

// Per-CTA dynamic shared layout (float offsets; vector targets 16B aligned)
#define OFF_WIH   0                             // 4000
#define OFF_WHH   (OFF_WIH + ROWS_LOC * PITCH)  // 4000
#define OFF_X     (OFF_WHH + ROWS_LOC * PITCH)  // 8000
#define OFF_H0    (OFF_X + IN)                  // 8008
#define OFF_FEAT  (OFF_H0 + 100)                // 8108 (mult of 4 -> 16B)
#define OFF_H1    (OFF_FEAT + FEAT)             // 8308
#define OFF_W2    (OFF_H1 + H1 + 2)             // 8360 (mult of 4 -> 16B)
#define SMEM_FLOATS (OFF_W2 + H2 * H1)          // 8860
#define SMEM_BYTES  (SMEM_FLOATS * 4)           // 35440

__device__ __forceinline__ float tanh_fast(float x) {
    float xc = fminf(fmaxf(x, -15.0f), 15.0f);
    float e = __expf(2.0f * xc);
    return __fdividef(e - 1.0f, e + 1.0f);
}
__device__ __forceinline__ float sigmoid_fast(float x) {
    float xc = fminf(fmaxf(x, -30.0f), 30.0f);
    return __fdividef(1.0f, 1.0f + __expf(-xc));
}
__device__ __forceinline__ uint32_t smem_u32(const void* p) {
    return (uint32_t)__cvta_generic_to_shared(p);
}
__device__ __forceinline__ void st_peer(uint32_t laddr, uint32_t peer, float v) {
    uint32_t rem;
    asm volatile("mapa.shared::cluster.u32 %0, %1, %2;"
                 : "=r"(rem) : "r"(laddr), "r"(peer));
    asm volatile("st.shared::cluster.u32 [%0], %1;"
                 :: "r"(rem), "r"(__float_as_uint(v)) : "memory");
}
__device__ __forceinline__ void cluster_sync_() {
    asm volatile("barrier.cluster.arrive.aligned;" ::: "memory");
    asm volatile("barrier.cluster.wait.aligned;" ::: "memory");
}
// ---- packed f32x2 helpers (sm_103a FFMA2 via PTX only) ----
__device__ __forceinline__ uint64_t pk2(float lo, float hi) {
    uint64_t r;
    asm("mov.b64 %0, {%1, %2};" : "=l"(r) : "f"(lo), "f"(hi));
    return r;
}
__device__ __forceinline__ uint64_t pkf2(float2 v) { return pk2(v.x, v.y); }
__device__ __forceinline__ float2 upk2(uint64_t v) {
    float2 r;
    asm("mov.b64 {%0, %1}, %2;" : "=f"(r.x), "=f"(r.y) : "l"(v));
    return r;
}
__device__ __forceinline__ uint64_t ffma2(uint64_t a, uint64_t b, uint64_t c) {
    uint64_t d;
    asm("fma.rn.f32x2 %0, %1, %2, %3;" : "=l"(d) : "l"(a), "l"(b), "l"(c));
    return d;
}

template <bool VEC>
__global__ __launch_bounds__(800, 1) __cluster_dims__(2, 1, 1)
void lstm_mlp_cluster(const float* __restrict__ x,
                      const float* __restrict__ h0,
                      const float* __restrict__ c0,
                      const float* __restrict__ W_ih,
                      const float* __restrict__ W_hh,
                      const float* __restrict__ b_ih,
                      const float* __restrict__ b_hh,
                      const float* __restrict__ W1,
                      const float* __restrict__ b1,
                      const float* __restrict__ W2,
                      const float* __restrict__ b2,
                      const float* __restrict__ W3,
                      const float* __restrict__ b3,
                      float* __restrict__ out)
{
    extern __shared__ float sm[];
    const int t = threadIdx.x;
    const int lane = t & 31;
    uint32_t rank;
    asm("mov.u32 %0, %%cluster_ctarank;" : "=r"(rank));
    const uint32_t peer = rank ^ 1u;

    // ---- Stage-1 mapping (warps 0..12): lane = 4q+g -> gate g of o = 8w+q
    const int o = (t >> 5) * 8 + (lane >> 2);
    const int g = lane & 3;
    const int oc = (o < 100) ? o : 99;           // clamp for safe reads
    const int cl = oc / 10;
    const int jj = oc - cl * 10;
    const int lr = cl * 40 + g * 10 + jj;        // local gate row 0..399

    // ---- Stage-3 mapping: 16 lanes/row, 50 rows = exact full block (both CTAs)
    const int lane16 = t & 15;
    const int row = t >> 4;                      // 0..49

    // ================= Entry staging =================
    if (VEC) {
        // W_hh half: straight float4 copy (4000 floats = 1000 float4)
        const float4* wh4 = (const float4*)(W_hh + rank * (ROWS_LOC * HID));
        ((float4*)(sm + OFF_WHH))[t] = wh4[t];
        if (t < 200) ((float4*)(sm + OFF_WHH))[800 + t] = wh4[800 + t];
        // W_ih half: 800 float4, scatter 8->10 pitch via two STS.64
        const float4* wi4 = (const float4*)(W_ih + rank * (ROWS_LOC * IN));
        {
            float4 v = wi4[t];
            int e = t * 4;                                   // e&7 in {0,4}
            float2* dst = (float2*)(sm + OFF_WIH + (e >> 3) * PITCH + (e & 7));
            dst[0] = make_float2(v.x, v.y);
            dst[1] = make_float2(v.z, v.w);
        }
        if (t < 125)                     // W2 on BOTH CTAs (redundant tail)
            ((float4*)(sm + OFF_W2))[t] = ((const float4*)W2)[t];
        if (t < 25)
            ((float4*)(sm + OFF_H0))[t] =
                ((const float4*)(h0 + (int)rank * 100))[t];
    } else {
        const float* wihg = W_ih + rank * (ROWS_LOC * IN);
        #pragma unroll
        for (int k = 0; k < 4; ++k) {
            int q = t + 800 * k;
            sm[OFF_WIH + (q >> 3) * PITCH + (q & 7)] = wihg[q];
        }
        const float* whhg = W_hh + rank * (ROWS_LOC * HID);
        #pragma unroll
        for (int k = 0; k < 5; ++k) {
            int q = t + 800 * k;
            sm[OFF_WHH + q] = whhg[q];
        }
        if (t < H2 * H1) sm[OFF_W2 + t] = W2[t];
        if (t < 100) sm[OFF_H0 + t] = h0[(int)rank * 100 + t];
    }

    // Stage-1 per-thread operands
    float bias = 0.0f, c0r = 0.0f;
    if (t < 416) {
        int gr = (int)rank * ROWS_LOC + lr;
        bias = b_ih[gr] + b_hh[gr];
        if (o < 100) c0r = c0[(int)rank * 100 + o];
    }

    // Stage-3 W1 row slice in registers (all 800 threads, both CTAs)
    float4 w1q[3];
    float  w1s[12];
    float4 w1tail = make_float4(0.f, 0.f, 0.f, 0.f);
    float  w1t = 0.0f, b1r = 0.0f;
    {
        if (VEC) {
            const float4* w4p = (const float4*)(W1 + row * FEAT);  // 800B mult
            #pragma unroll
            for (int u = 0; u < 3; ++u) w1q[u] = w4p[lane16 + (u << 4)];
            if (lane16 < 2) w1tail = w4p[48 + lane16];
        } else {
            const float* w1p = W1 + row * FEAT + lane16;
            #pragma unroll
            for (int u = 0; u < 12; ++u) w1s[u] = w1p[u << 4];
            w1t = (lane16 < 8) ? w1p[192] : 0.0f;
        }
        b1r = (lane16 == 0) ? b1[row] : 0.0f;
    }

    // Stage-4/5 operands (both CTAs; only rank 0 writes out)
    float b2r = 0.0f, w3r = 0.0f, b3r = 0.0f;
    if (t < H2) { b2r = b2[t]; w3r = W3[t]; }
    if (t == 0) b3r = b3[0];
    if (t < IN) sm[OFF_X + t] = x[t];
    __syncthreads();   // CTA-local staging visible

    // ======== Stage 1+2: packed-f32x2 gate dots + activations + update ========
    if (t < 416) {
        const float2* wi2 = (const float2*)(sm + OFF_WIH + lr * PITCH);
        const float2* wh2 = (const float2*)(sm + OFF_WHH + lr * PITCH);
        const float2* x2  = (const float2*)(sm + OFF_X);
        const float2* h2v = (const float2*)(sm + OFF_H0 + cl * HID);
        uint64_t acc2 = pk2(bias, 0.0f);
        #pragma unroll
        for (int i = 0; i < 4; ++i)
            acc2 = ffma2(pkf2(wi2[i]), pkf2(x2[i]), acc2);
        #pragma unroll
        for (int k = 0; k < 5; ++k)
            acc2 = ffma2(pkf2(wh2[k]), pkf2(h2v[k]), acc2);
        float2 ar = upk2(acc2);
        float acc = ar.x + ar.y;

        float vin = (g == 2) ? (acc + acc) : acc;          // tanh = 2*sig(2x)-1
        float s   = sigmoid_fast(vin);
        float act = (g == 2) ? fmaf(2.0f, s, -1.0f) : s;

        const int base = lane & ~3;
        float ia = __shfl_sync(0xffffffffu, act, base);
        float fa = __shfl_sync(0xffffffffu, act, base + 1);
        float ga = __shfl_sync(0xffffffffu, act, base + 2);
        float oa = __shfl_sync(0xffffffffu, act, base + 3);
        if (g == 0 && o < 100) {
            float c = fmaf(fa, c0r, ia * ga);
            float h = oa * tanh_fast(c);
            int fidx = (rank == 1) ? o : (100 + o);        // gen bank first
            float* dst = sm + OFF_FEAT + fidx;
            *dst = h;                                      // local copy
            st_peer(smem_u32(dst), peer, h);               // peer copy
        }
    }
    cluster_sync_();   // the ONLY cluster barrier: full feat visible in both CTAs

    // ======== Stage 3: ALL 50 h1 rows on BOTH CTAs (redundant, balanced) =====
    {
        float sum = 0.0f;
        if (VEC) {
            const float4* f4 = (const float4*)(sm + OFF_FEAT);
            #pragma unroll
            for (int u = 0; u < 3; ++u) {
                float4 f = f4[lane16 + (u << 4)];
                float4 w = w1q[u];
                sum = fmaf(w.x, f.x, sum);
                sum = fmaf(w.y, f.y, sum);
                sum = fmaf(w.z, f.z, sum);
                sum = fmaf(w.w, f.w, sum);
            }
            if (lane16 < 2) {
                float4 f = f4[48 + lane16];
                sum = fmaf(w1tail.x, f.x, sum);
                sum = fmaf(w1tail.y, f.y, sum);
                sum = fmaf(w1tail.z, f.z, sum);
                sum = fmaf(w1tail.w, f.w, sum);
            }
        } else {
            const float* f = sm + OFF_FEAT;
            #pragma unroll
            for (int u = 0; u < 12; ++u)
                sum = fmaf(w1s[u], f[lane16 + (u << 4)], sum);
            if (lane16 < 8)
                sum = fmaf(w1t, f[192 + lane16], sum);
        }
        sum += __shfl_xor_sync(0xffffffffu, sum, 8);
        sum += __shfl_xor_sync(0xffffffffu, sum, 4);
        sum += __shfl_xor_sync(0xffffffffu, sum, 2);
        sum += __shfl_xor_sync(0xffffffffu, sum, 1);
        if (lane16 == 0) sm[OFF_H1 + row] = tanh_fast(sum + b1r);
    }
    __syncthreads();   // CTA-local: all 50 h1 values ready (no cluster traffic)

    // ======== Stage 4+5 (warp 0, both CTAs; rank 0 writes) ========
    if (t < 32) {
        float sum = 0.0f;
        if (t < H2) {
            const float* wv = sm + OFF_W2 + t * H1;   // banks 18r mod 32 distinct
            const float* hv = sm + OFF_H1;            // broadcast reads
            #pragma unroll
            for (int i = 0; i < H1; ++i) sum = fmaf(wv[i], hv[i], sum);
        }
        float p = (t < H2) ? w3r * tanh_fast(sum + b2r) : 0.0f;
        #pragma unroll
        for (int m = 16; m > 0; m >>= 1)
            p += __shfl_xor_sync(0xffffffffu, p, m);
        if (t == 0 && rank == 0) out[0] = tanh_fast(p + b3r);
    }
}

static inline bool aligned16(const void* p) {
    return (((uintptr_t)p) & 15u) == 0;
}

extern "C" void kernel_launch(void* const* d_in, const int* in_sizes, int n_in,
                              void* d_out, int out_size) {
    (void)in_sizes; (void)n_in; (void)out_size;
    const float* x    = (const float*)d_in[0];
    const float* h0   = (const float*)d_in[1];
    const float* c0   = (const float*)d_in[2];
    const float* W_ih = (const float*)d_in[3];
    const float* W_hh = (const float*)d_in[4];
    const float* b_ih = (const float*)d_in[5];
    const float* b_hh = (const float*)d_in[6];
    const float* W1   = (const float*)d_in[7];
    const float* b1   = (const float*)d_in[8];
    const float* W2   = (const float*)d_in[9];
    const float* b2   = (const float*)d_in[10];
    const float* W3   = (const float*)d_in[11];
    const float* b3   = (const float*)d_in[12];
    float* out = (float*)d_out;

    static bool attr_set = false;
    if (!attr_set) {
        cudaFuncSetAttribute(lstm_mlp_cluster<true>,
                             cudaFuncAttributeMaxDynamicSharedMemorySize,
                             SMEM_BYTES);
        cudaFuncSetAttribute(lstm_mlp_cluster<false>,
                             cudaFuncAttributeMaxDynamicSharedMemorySize,
                             SMEM_BYTES);
        attr_set = true;
    }

    const bool vec = aligned16(W_ih) && aligned16(W_hh) && aligned16(W1) &&
                     aligned16(h0) && aligned16(W2);

    if (vec) {
        lstm_mlp_cluster<true><<<2, 800, SMEM_BYTES>>>(
            x, h0, c0, W_ih, W_hh, b_ih, b_hh, W1, b1, W2, b2, W3, b3, out);
    } else {
        lstm_mlp_cluster<false><<<2, 800, SMEM_BYTES>>>(
            x, h0, c0, W_ih, W_hh, b_ih, b_hh, W1, b1, W2, b2, W3, b3, out);
    }
}